// round 1
// baseline (speedup 1.0000x reference)
#include <cuda_runtime.h>
#include <stdint.h>

// DataEmbedder: out[row, 0:32]=emb0[lut0[ds[row,0]]], [32:96]=emb1[...],
// [96:112]=emb2[...], [112:120]=emb3[...], [120:128]=ds[row,4:12]
// rows = 64*4096 = 262144, out = rows*128 fp32.

#define ROWS (64 * 4096)

__global__ __launch_bounds__(256, 8)
void data_embedder_kernel(const float* __restrict__ dataset,
                          const float4* __restrict__ emb0,  // [1000, 8]  float4
                          const float4* __restrict__ emb1,  // [5000, 16] float4
                          const float4* __restrict__ emb2,  // [200, 4]   float4
                          const float4* __restrict__ emb3,  // [50, 2]    float4
                          const int* __restrict__ lut0,
                          const int* __restrict__ lut1,
                          const int* __restrict__ lut2,
                          const int* __restrict__ lut3,
                          float4* __restrict__ out)         // [rows, 32] float4
{
    const int warp_in_block = threadIdx.x >> 5;
    const int lane = threadIdx.x & 31;
    const long long row = (long long)blockIdx.x * 8 + warp_in_block;
    if (row >= ROWS) return;

    // dataset row: 12 floats = 3 float4, 16B-aligned (48B stride)
    const float4* drow = (const float4*)(dataset + row * 12LL);
    const float4 cats = __ldg(drow);  // cols 0..3: raw category ids (broadcast)

    float4 v;
    if (lane < 8) {
        int id = __ldg(&lut0[(int)cats.x]);
        v = __ldg(&emb0[(long long)id * 8 + lane]);
    } else if (lane < 24) {
        int id = __ldg(&lut1[(int)cats.y]);
        v = __ldg(&emb1[(long long)id * 16 + (lane - 8)]);
    } else if (lane < 28) {
        int id = __ldg(&lut2[(int)cats.z]);
        v = __ldg(&emb2[(long long)id * 4 + (lane - 24)]);
    } else if (lane < 30) {
        int id = __ldg(&lut3[(int)cats.w]);
        v = __ldg(&emb3[(long long)id * 2 + (lane - 28)]);
    } else {
        // lane 30 -> dataset cols 4..7 (drow[1]); lane 31 -> cols 8..11 (drow[2])
        v = __ldg(&drow[lane - 29]);
    }

    out[row * 32 + lane] = v;
}

extern "C" void kernel_launch(void* const* d_in, const int* in_sizes, int n_in,
                              void* d_out, int out_size)
{
    // Identify inputs by unique element counts (robust to metadata ordering).
    const float* dataset = nullptr;
    const void *e0 = nullptr, *e1 = nullptr, *e2 = nullptr, *e3 = nullptr;
    const int *l0 = nullptr, *l1 = nullptr, *l2 = nullptr, *l3 = nullptr;
    for (int i = 0; i < n_in; i++) {
        switch (in_sizes[i]) {
            case 64 * 4096 * 12: dataset = (const float*)d_in[i]; break;
            case 1000 * 32:      e0 = d_in[i]; break;
            case 5000 * 64:      e1 = d_in[i]; break;
            case 200 * 16:       e2 = d_in[i]; break;
            case 50 * 8:         e3 = d_in[i]; break;
            case 1000:           l0 = (const int*)d_in[i]; break;
            case 5000:           l1 = (const int*)d_in[i]; break;
            case 200:            l2 = (const int*)d_in[i]; break;
            case 50:             l3 = (const int*)d_in[i]; break;
            default: break;
        }
    }

    // 8 rows (warps) per 256-thread block
    const int blocks = ROWS / 8;
    data_embedder_kernel<<<blocks, 256>>>(
        dataset,
        (const float4*)e0, (const float4*)e1, (const float4*)e2, (const float4*)e3,
        l0, l1, l2, l3,
        (float4*)d_out);
}